// round 10
// baseline (speedup 1.0000x reference)
#include <cuda_runtime.h>
#include <math.h>
#include <float.h>
#include <stdint.h>

#define S   4096
#define MD  2048
#define E   32
#define CAP 256
#define ROW (E * CAP)                    // 8192 floats per token row-group
#define CW_ELEMS ((size_t)S * E * CAP)   // 33554432

// ---------------- device scratch (no allocations allowed) ----------------
#define SPLITS 8
__device__ float g_part[SPLITS][S * E];   // split-K partial logits (4MB)

__device__ int   g_top_i1[S];
__device__ int   g_top_i2[S];
__device__ float g_top_v1[S];
__device__ float g_top_v2[S];
__device__ float g_top_g1[S];
__device__ float g_top_g2[S];
__device__ int   g_slot[S * 2];

#define NB2 128
__device__ float g_pgsum[NB2 * E];
__device__ int   g_pcnt[NB2 * E];
__device__ float g_laux;
__device__ float g_ec[E];

// ---------------- K1a: split-K GEMM (partial logits) ----------------------
#define K1_THREADS 128
#define KC 64
#define KSPAN (MD / SPLITS)   // 256
#define LD4 17                // float4 row stride (16 + 1 pad)

__global__ __launch_bounds__(K1_THREADS)
void k1a_gemm(const float* __restrict__ x, const float* __restrict__ wg)
{
    __shared__ float4 xs[32 * LD4];
    __shared__ float4 ws[32 * LD4];

    const int split = blockIdx.x & (SPLITS - 1);
    const int tgrp  = blockIdx.x >> 3;
    const int tid = threadIdx.x;
    const int tx  = tid & 7;    // expert group (4 experts)
    const int ty  = tid >> 3;   // token group  (2 tokens), 0..15
    const int t0  = tgrp * 32;

    float acc[2][4];
#pragma unroll
    for (int i = 0; i < 2; i++)
#pragma unroll
        for (int j = 0; j < 4; j++) acc[i][j] = 0.f;

    const float4* x4 = (const float4*)x;
    const float4* w4 = (const float4*)wg;

    const int kbeg = split * KSPAN;
    for (int kc = kbeg; kc < kbeg + KSPAN; kc += KC) {
        const int kc4 = kc >> 2;
        // 32 rows x 16 float4 cols, 128 threads -> 4 each
        for (int i = tid; i < 32 * 16; i += K1_THREADS) {
            int r = i >> 4, c = i & 15;
            xs[r * LD4 + c] = x4[(size_t)(t0 + r) * (MD / 4) + kc4 + c];
            ws[r * LD4 + c] = w4[(size_t)r       * (MD / 4) + kc4 + c];
        }
        __syncthreads();

#pragma unroll
        for (int k4 = 0; k4 < 16; k4++) {
            float4 a0 = xs[(2 * ty)     * LD4 + k4];
            float4 a1 = xs[(2 * ty + 1) * LD4 + k4];
#pragma unroll
            for (int j = 0; j < 4; j++) {
                float4 b = ws[(4 * tx + j) * LD4 + k4];
                acc[0][j] = fmaf(a0.x, b.x, fmaf(a0.y, b.y, fmaf(a0.z, b.z, fmaf(a0.w, b.w, acc[0][j]))));
                acc[1][j] = fmaf(a1.x, b.x, fmaf(a1.y, b.y, fmaf(a1.z, b.z, fmaf(a1.w, b.w, acc[1][j]))));
            }
        }
        __syncthreads();
    }

#pragma unroll
    for (int i = 0; i < 2; i++)
#pragma unroll
        for (int j = 0; j < 4; j++)
            g_part[split][(size_t)(t0 + 2 * ty + i) * E + (4 * tx + j)] = acc[i][j];
}

// ---------------- K1b: reduce splits + top2/softmax + partial sums --------
__global__ __launch_bounds__(1024)
void k1b_topk()
{
    const int warp = threadIdx.x >> 5;
    const int lane = threadIdx.x & 31;
    const int t = blockIdx.x * 32 + warp;
    const size_t o = (size_t)t * E + lane;

    float l = 0.f;
#pragma unroll
    for (int sp = 0; sp < SPLITS; sp++) l += g_part[sp][o];

    // top-1 (tie -> lower index, matching jax.lax.top_k)
    float v1 = l; int i1 = lane;
#pragma unroll
    for (int off = 16; off; off >>= 1) {
        float ov = __shfl_xor_sync(0xffffffffu, v1, off);
        int   oi = __shfl_xor_sync(0xffffffffu, i1, off);
        if (ov > v1 || (ov == v1 && oi < i1)) { v1 = ov; i1 = oi; }
    }
    // top-2
    float l2 = (lane == i1) ? -FLT_MAX : l;
    float v2 = l2; int i2 = lane;
#pragma unroll
    for (int off = 16; off; off >>= 1) {
        float ov = __shfl_xor_sync(0xffffffffu, v2, off);
        int   oi = __shfl_xor_sync(0xffffffffu, i2, off);
        if (ov > v2 || (ov == v2 && oi < i2)) { v2 = ov; i2 = oi; }
    }

    // softmax over the 32 logits
    float p = expf(l - v1);
    float sum = p;
#pragma unroll
    for (int off = 16; off; off >>= 1) sum += __shfl_xor_sync(0xffffffffu, sum, off);
    float gate = p / sum;

    float g1v = __shfl_sync(0xffffffffu, gate, i1);
    float g2v = __shfl_sync(0xffffffffu, gate, i2);

    if (lane == 0) {
        g_top_i1[t] = i1;  g_top_i2[t] = i2;
        g_top_v1[t] = v1;  g_top_v2[t] = v2;
        g_top_g1[t] = g1v; g_top_g2[t] = g2v;
        g_slot[2 * t]     = -1;
        g_slot[2 * t + 1] = -1;
    }

    // deterministic per-block reduction of gate sums / counts
    __shared__ float gm[32][33];
    __shared__ int   im[32];
    gm[warp][lane] = gate;
    if (lane == 0) im[warp] = i1 | (i2 << 8);
    __syncthreads();

    if (warp == 0) {
        float s = 0.f; int c = 0;
#pragma unroll 8
        for (int w = 0; w < 32; w++) {
            s += gm[w][lane];
            int pk = im[w];
            c += ((pk & 255) == lane) + ((pk >> 8) == lane);
        }
        g_pgsum[blockIdx.x * E + lane] = s;
        g_pcnt [blockIdx.x * E + lane] = c;
    }
}

// ---------------- K3: capacity filter + slot assignment (+laux reduce) ----
__global__ __launch_bounds__(256)
void k3_capacity()
{
    if (blockIdx.x == E) {
        // reduce partial gate sums / counts -> g_laux, g_ec
        __shared__ float rs[8][32];
        __shared__ int   rc[8][32];
        int e  = threadIdx.x & 31;
        int ch = threadIdx.x >> 5;
        float s = 0.f; int c = 0;
        for (int b = ch; b < NB2; b += 8) {
            s += g_pgsum[b * E + e];
            c += g_pcnt [b * E + e];
        }
        rs[ch][e] = s; rc[ch][e] = c;
        __syncthreads();
        if (threadIdx.x < 32) {
            float st = 0.f; int ct = 0;
#pragma unroll
            for (int k = 0; k < 8; k++) { st += rs[k][threadIdx.x]; ct += rc[k][threadIdx.x]; }
            g_ec[threadIdx.x] = (float)ct;
            float prod = (st / (float)S) * ((float)ct / (float)S);
#pragma unroll
            for (int off = 16; off; off >>= 1) prod += __shfl_xor_sync(0xffffffffu, prod, off);
            if (threadIdx.x == 0) g_laux = prod * 16.0f;   // *E*E/K/E = *16
        }
        return;
    }

    const int e = blockIdx.x;
    __shared__ float vals[S];
    __shared__ int   s_cnt;
    __shared__ float s_thr;
    __shared__ int   warp_tot[8];
    __shared__ int   s_running;

    if (threadIdx.x == 0) { s_cnt = 0; s_running = 0; }
    __syncthreads();

    // gather positive selected logits for this expert
    for (int t = threadIdx.x; t < S; t += 256) {
        int i1 = g_top_i1[t], i2 = g_top_i2[t];
        float v; int hit = 0;
        if (i1 == e)      { v = g_top_v1[t]; hit = 1; }
        else if (i2 == e) { v = g_top_v2[t]; hit = 1; }
        else v = 0.f;
        if (hit && v > 0.f) {
            int p = atomicAdd(&s_cnt, 1);
            vals[p] = v;
        }
    }
    __syncthreads();

    int n = s_cnt;
    if (n <= CAP) {
        if (threadIdx.x == 0) s_thr = -FLT_MAX;
        __syncthreads();
    } else {
        int n2 = 1; while (n2 < n) n2 <<= 1;
        for (int i = n + threadIdx.x; i < n2; i += 256) vals[i] = -FLT_MAX;
        __syncthreads();
        // bitonic sort, descending
        for (int k = 2; k <= n2; k <<= 1) {
            for (int j = k >> 1; j > 0; j >>= 1) {
                for (int i = threadIdx.x; i < n2; i += 256) {
                    int ixj = i ^ j;
                    if (ixj > i) {
                        float a = vals[i], b = vals[ixj];
                        bool desc = ((i & k) == 0);
                        if (desc ? (a < b) : (a > b)) { vals[i] = b; vals[ixj] = a; }
                    }
                }
                __syncthreads();
            }
        }
        if (threadIdx.x == 0) s_thr = vals[CAP - 1];
        __syncthreads();
    }
    float thr = s_thr;

    // token-order scan: assign cumulative slots
    const int lane = threadIdx.x & 31;
    const int w    = threadIdx.x >> 5;
    for (int base = 0; base < S; base += 256) {
        int t = base + threadIdx.x;
        int i1 = g_top_i1[t], i2 = g_top_i2[t];
        int j = (i1 == e) ? 0 : ((i2 == e) ? 1 : -1);
        float v = (j == 0) ? g_top_v1[t] : ((j == 1) ? g_top_v2[t] : 0.f);
        int kept = (j >= 0 && v > 0.f && v >= thr) ? 1 : 0;

        unsigned bal = __ballot_sync(0xffffffffu, kept);
        int pre = __popc(bal & ((1u << lane) - 1u));
        if (lane == 31) warp_tot[w] = pre + kept;
        __syncthreads();

        int woff = 0;
#pragma unroll
        for (int ww = 0; ww < 8; ww++) woff += (ww < w) ? warp_tot[ww] : 0;
        int slot = s_running + woff + pre;
        if (kept) g_slot[2 * t + j] = slot;
        __syncthreads();

        if (threadIdx.x == 0) {
            int tot = 0;
#pragma unroll
            for (int ww = 0; ww < 8; ww++) tot += warp_tot[ww];
            s_running += tot;
        }
        __syncthreads();
    }
}

// ---------------- K_fill: streaming zero-fill (side stream) ---------------
#define CHUNK 65536LL   // floats per block (256KB)

__global__ __launch_bounds__(256)
void k_fill(float* __restrict__ out, long long osz)
{
    const long long lo = (long long)blockIdx.x * CHUNK;
    const long long hi = min(lo + CHUNK, osz);
    long long lo4 = lo >> 2;
    long long hi4 = hi >> 2;
    float4 z = make_float4(0.f, 0.f, 0.f, 0.f);
    float4* o4 = (float4*)out;
    for (long long i = lo4 + threadIdx.x; i < hi4; i += 256)
        __stcs(o4 + i, z);
    if (hi == osz) {
        for (long long i = (hi4 << 2) + threadIdx.x; i < osz; i += 256)
            out[i] = 0.f;
    }
}

// ---------------- K4: scatter-only (after fill + gating) ------------------
__global__ __launch_bounds__(256)
void k4_scatter(float* __restrict__ out,
                long long o_laux, long long o_cw,
                long long o_dm,   long long o_ec)
{
    if (blockIdx.x == 0) {
        if (threadIdx.x == 32 && o_laux >= 0) out[o_laux] = g_laux;
        if (threadIdx.x < 32 && o_ec >= 0)    out[o_ec + threadIdx.x] = g_ec[threadIdx.x];
    }

    int t = blockIdx.x * 256 + threadIdx.x;
    if (t >= S) return;

    int   i1 = g_top_i1[t], i2 = g_top_i2[t];
    float g1 = g_top_g1[t], g2 = g_top_g2[t];
    int   s1 = g_slot[2 * t], s2 = g_slot[2 * t + 1];
    bool  k1 = (s1 >= 0), k2 = (s2 >= 0);

    float denom = (k1 ? g1 : 0.f) + (k2 ? g2 : 0.f);
    if (denom <= 0.f) return;
    int c = (k1 ? s1 : 0) + (k2 ? s2 : 0);   // locations_s = SUM of slots
    if (c >= CAP) return;                     // one_hot out of range

    if (k1) {
        long long idx = ((long long)t * E + i1) * CAP + c;
        if (o_cw >= 0) out[o_cw + idx] = g1 / denom;
        if (o_dm >= 0) out[o_dm + idx] = 1.0f;
    }
    if (k2) {
        long long idx = ((long long)t * E + i2) * CAP + c;
        if (o_cw >= 0) out[o_cw + idx] = g2 / denom;
        if (o_dm >= 0) out[o_dm + idx] = 1.0f;
    }
}

// ---------------- launch ---------------------------------------------------
extern "C" void kernel_launch(void* const* d_in, const int* in_sizes, int n_in,
                              void* d_out, int out_size)
{
    const float* x  = (const float*)d_in[0];
    const float* wg = (const float*)d_in[1];
    float* out = (float*)d_out;

    const long long CW = (long long)CW_ELEMS;
    long long o_laux = -1, o_cw = -1, o_dm = -1, o_ec = -1;

    long long osz = (long long)out_size;
    if (osz == 1 + 2 * CW + 32) {
        o_laux = 0;
        o_cw   = 1;
        o_dm   = 1 + CW;
        o_ec   = 1 + 2 * CW;
    } else if (osz == 2 * CW) {
        o_cw = 0; o_dm = CW;
    } else if (osz == CW) {
        o_cw = 0;
    } else {
        o_laux = 0;
        o_cw   = 1;
        if (osz > 1 + CW)     o_dm = 1 + CW;
        if (osz > 1 + 2 * CW) o_ec = 1 + 2 * CW;
    }

    // One-time host-object creation (no device memory).
    static cudaStream_t s_side = nullptr;
    static cudaEvent_t  s_fork = nullptr, s_join = nullptr;
    if (s_side == nullptr) {
        cudaStreamCreateWithFlags(&s_side, cudaStreamNonBlocking);
        cudaEventCreateWithFlags(&s_fork, cudaEventDisableTiming);
        cudaEventCreateWithFlags(&s_join, cudaEventDisableTiming);
    }

    // Fork: DRAM-bound zero-fill (issue ~4%) overlaps the compute-bound
    // gating pipeline on the main stream.
    cudaEventRecord(s_fork, 0);
    cudaStreamWaitEvent(s_side, s_fork, 0);
    int fill_blocks = (int)((osz + CHUNK - 1) / CHUNK);
    k_fill<<<fill_blocks, 256, 0, s_side>>>(out, osz);
    cudaEventRecord(s_join, s_side);

    // Main pipeline (doesn't touch `out` until the scatter).
    k1a_gemm<<<128 * SPLITS, K1_THREADS>>>(x, wg);
    k1b_topk<<<NB2, 1024>>>();
    k3_capacity<<<E + 1, 256>>>();

    // Join, then patch the ~8k nonzeros + scalars.
    cudaStreamWaitEvent(0, s_join, 0);
    k4_scatter<<<(S + 255) / 256, 256>>>(out, o_laux, o_cw, o_dm, o_ec);
}

// round 12
// speedup vs baseline: 1.8466x; 1.8466x over previous
#include <cuda_runtime.h>
#include <math.h>
#include <float.h>
#include <stdint.h>

#define S   4096
#define MD  2048
#define E   32
#define CAP 256
#define ROW (E * CAP)                    // 8192 floats per token row-group
#define CW_ELEMS ((size_t)S * E * CAP)   // 33554432

// ---------------- device scratch (no allocations allowed) ----------------
#define SPLITS 8
__device__ float g_part[SPLITS][S * E];   // split-K partial logits (4MB)

__device__ int   g_top_i1[S];
__device__ int   g_top_i2[S];
__device__ float g_top_v1[S];
__device__ float g_top_v2[S];
__device__ float g_top_g1[S];
__device__ float g_top_g2[S];
__device__ int   g_slot[S * 2];

#define NB2 128
__device__ float g_pgsum[NB2 * E];
__device__ int   g_pcnt[NB2 * E];
__device__ float g_laux;
__device__ float g_ec[E];

// ---------------- K1a: split-K GEMM (partial logits) ----------------------
#define K1_THREADS 128
#define KC 64
#define KSPAN (MD / SPLITS)   // 256
#define LD4 17                // float4 row stride (16 + 1 pad)

__global__ __launch_bounds__(K1_THREADS)
void k1a_gemm(const float* __restrict__ x, const float* __restrict__ wg)
{
    __shared__ float4 xs[32 * LD4];
    __shared__ float4 ws[32 * LD4];

    const int split = blockIdx.x & (SPLITS - 1);
    const int tgrp  = blockIdx.x >> 3;
    const int tid = threadIdx.x;
    const int tx  = tid & 7;    // expert lane: handles experts tx, tx+8, tx+16, tx+24
    const int ty  = tid >> 3;   // token group (2 tokens), 0..15
    const int t0  = tgrp * 32;

    float acc[2][4];
#pragma unroll
    for (int i = 0; i < 2; i++)
#pragma unroll
        for (int j = 0; j < 4; j++) acc[i][j] = 0.f;

    const float4* x4 = (const float4*)x;
    const float4* w4 = (const float4*)wg;

    const int kbeg = split * KSPAN;
    for (int kc = kbeg; kc < kbeg + KSPAN; kc += KC) {
        const int kc4 = kc >> 2;
        for (int i = tid; i < 32 * 16; i += K1_THREADS) {
            int r = i >> 4, c = i & 15;
            xs[r * LD4 + c] = x4[(size_t)(t0 + r) * (MD / 4) + kc4 + c];
            ws[r * LD4 + c] = w4[(size_t)r       * (MD / 4) + kc4 + c];
        }
        __syncthreads();

#pragma unroll
        for (int k4 = 0; k4 < 16; k4++) {
            float4 a0 = xs[(2 * ty)     * LD4 + k4];
            float4 a1 = xs[(2 * ty + 1) * LD4 + k4];
#pragma unroll
            for (int j = 0; j < 4; j++) {
                // strided expert rows: consecutive 8 rows per phase -> conflict-free
                float4 b = ws[(tx + 8 * j) * LD4 + k4];
                acc[0][j] = fmaf(a0.x, b.x, fmaf(a0.y, b.y, fmaf(a0.z, b.z, fmaf(a0.w, b.w, acc[0][j]))));
                acc[1][j] = fmaf(a1.x, b.x, fmaf(a1.y, b.y, fmaf(a1.z, b.z, fmaf(a1.w, b.w, acc[1][j]))));
            }
        }
        __syncthreads();
    }

#pragma unroll
    for (int i = 0; i < 2; i++)
#pragma unroll
        for (int j = 0; j < 4; j++)
            g_part[split][(size_t)(t0 + 2 * ty + i) * E + (tx + 8 * j)] = acc[i][j];
}

// ---------------- K1b: reduce splits + top2/softmax + partial sums --------
__global__ __launch_bounds__(1024)
void k1b_topk()
{
    const int warp = threadIdx.x >> 5;
    const int lane = threadIdx.x & 31;
    const int t = blockIdx.x * 32 + warp;
    const size_t o = (size_t)t * E + lane;

    float l = 0.f;
#pragma unroll
    for (int sp = 0; sp < SPLITS; sp++) l += g_part[sp][o];

    // top-1 (tie -> lower index, matching jax.lax.top_k)
    float v1 = l; int i1 = lane;
#pragma unroll
    for (int off = 16; off; off >>= 1) {
        float ov = __shfl_xor_sync(0xffffffffu, v1, off);
        int   oi = __shfl_xor_sync(0xffffffffu, i1, off);
        if (ov > v1 || (ov == v1 && oi < i1)) { v1 = ov; i1 = oi; }
    }
    // top-2
    float l2 = (lane == i1) ? -FLT_MAX : l;
    float v2 = l2; int i2 = lane;
#pragma unroll
    for (int off = 16; off; off >>= 1) {
        float ov = __shfl_xor_sync(0xffffffffu, v2, off);
        int   oi = __shfl_xor_sync(0xffffffffu, i2, off);
        if (ov > v2 || (ov == v2 && oi < i2)) { v2 = ov; i2 = oi; }
    }

    // softmax over the 32 logits
    float p = expf(l - v1);
    float sum = p;
#pragma unroll
    for (int off = 16; off; off >>= 1) sum += __shfl_xor_sync(0xffffffffu, sum, off);
    float gate = p / sum;

    float g1v = __shfl_sync(0xffffffffu, gate, i1);
    float g2v = __shfl_sync(0xffffffffu, gate, i2);

    if (lane == 0) {
        g_top_i1[t] = i1;  g_top_i2[t] = i2;
        g_top_v1[t] = v1;  g_top_v2[t] = v2;
        g_top_g1[t] = g1v; g_top_g2[t] = g2v;
        g_slot[2 * t]     = -1;
        g_slot[2 * t + 1] = -1;
    }

    // deterministic per-block reduction of gate sums / counts
    __shared__ float gm[32][33];
    __shared__ int   im[32];
    gm[warp][lane] = gate;
    if (lane == 0) im[warp] = i1 | (i2 << 8);
    __syncthreads();

    if (warp == 0) {
        float s = 0.f; int c = 0;
#pragma unroll 8
        for (int w = 0; w < 32; w++) {
            s += gm[w][lane];
            int pk = im[w];
            c += ((pk & 255) == lane) + ((pk >> 8) == lane);
        }
        g_pgsum[blockIdx.x * E + lane] = s;
        g_pcnt [blockIdx.x * E + lane] = c;
    }
}

// ---------------- K3: capacity filter + slot assignment (+laux reduce) ----
// 1024 threads; thread tid owns tokens [4*tid, 4*tid+4). Single block-scan.
#define K3_T 1024
#define TPT  (S / K3_T)   // 4 tokens per thread

__global__ __launch_bounds__(K3_T)
void k3_capacity()
{
    const int tid  = threadIdx.x;
    const int lane = tid & 31;
    const int warp = tid >> 5;

    if (blockIdx.x == E) {
        // reduce partial gate sums / counts -> g_laux, g_ec
        __shared__ float rs[32][33];
        __shared__ int   rc[32][33];
        float s = 0.f; int c = 0;
        for (int b = warp; b < NB2; b += 32) {
            s += g_pgsum[b * E + lane];
            c += g_pcnt [b * E + lane];
        }
        rs[warp][lane] = s; rc[warp][lane] = c;
        __syncthreads();
        if (tid < 32) {
            float st = 0.f; int ct = 0;
#pragma unroll
            for (int k = 0; k < 32; k++) { st += rs[k][tid]; ct += rc[k][tid]; }
            g_ec[tid] = (float)ct;
            float prod = (st / (float)S) * ((float)ct / (float)S);
#pragma unroll
            for (int off = 16; off; off >>= 1) prod += __shfl_xor_sync(0xffffffffu, prod, off);
            if (tid == 0) g_laux = prod * 16.0f;   // *E*E/K/E = *16
        }
        return;
    }

    const int e = blockIdx.x;
    __shared__ float vals[S];
    __shared__ int   s_cnt;
    __shared__ float s_thr;
    __shared__ int   wtot[32];
    __shared__ int   wbase[32];

    if (tid == 0) s_cnt = 0;
    __syncthreads();

    // per-thread candidate gather (order-free; only used for threshold)
    float myv[TPT];
    int   myj[TPT];
#pragma unroll
    for (int k = 0; k < TPT; k++) {
        int t = tid * TPT + k;
        int i1 = g_top_i1[t], i2 = g_top_i2[t];
        int j = (i1 == e) ? 0 : ((i2 == e) ? 1 : -1);
        float v = (j == 0) ? g_top_v1[t] : ((j == 1) ? g_top_v2[t] : 0.f);
        bool cand = (j >= 0 && v > 0.f);
        myj[k] = cand ? j : -1;
        myv[k] = v;
        if (cand) {
            int p = atomicAdd(&s_cnt, 1);
            vals[p] = v;
        }
    }
    __syncthreads();

    const int n = s_cnt;
    if (n > CAP) {
        int n2 = 1; while (n2 < n) n2 <<= 1;
        for (int i = n + tid; i < n2; i += K3_T) vals[i] = -FLT_MAX;
        __syncthreads();
        // bitonic sort, descending, 1024 threads
        for (int k = 2; k <= n2; k <<= 1) {
            for (int j = k >> 1; j > 0; j >>= 1) {
                for (int i = tid; i < n2; i += K3_T) {
                    int ixj = i ^ j;
                    if (ixj > i) {
                        float a = vals[i], b = vals[ixj];
                        bool desc = ((i & k) == 0);
                        if (desc ? (a < b) : (a > b)) { vals[i] = b; vals[ixj] = a; }
                    }
                }
                __syncthreads();
            }
        }
    }
    if (tid == 0) s_thr = (n > CAP) ? vals[CAP - 1] : -FLT_MAX;
    __syncthreads();
    const float thr = s_thr;

    // kept flags + per-thread count
    int kept = 0;
    bool kf[TPT];
#pragma unroll
    for (int k = 0; k < TPT; k++) {
        kf[k] = (myj[k] >= 0) && (myv[k] >= thr);
        kept += kf[k];
    }

    // warp inclusive scan of per-thread counts
    int inc = kept;
#pragma unroll
    for (int off = 1; off < 32; off <<= 1) {
        int nb = __shfl_up_sync(0xffffffffu, inc, off);
        if (lane >= off) inc += nb;
    }
    int exc = inc - kept;
    if (lane == 31) wtot[warp] = inc;
    __syncthreads();

    if (warp == 0) {
        int v = wtot[lane];
        int iv = v;
#pragma unroll
        for (int off = 1; off < 32; off <<= 1) {
            int nb = __shfl_up_sync(0xffffffffu, iv, off);
            if (lane >= off) iv += nb;
        }
        wbase[lane] = iv - v;
    }
    __syncthreads();

    int slot = wbase[warp] + exc;
#pragma unroll
    for (int k = 0; k < TPT; k++) {
        if (kf[k]) {
            int t = tid * TPT + k;
            g_slot[2 * t + myj[k]] = slot++;
        }
    }
}

// ---------------- K4: fused zero-fill + scatter ---------------------------
#define CHUNK 65536LL   // floats per block (256KB)

__device__ __forceinline__ void patch_token(int t, float* out,
                                            long long lo, long long hi,
                                            long long base, bool weighted)
{
    if (t < 0 || t >= S) return;
    int   i1 = g_top_i1[t], i2 = g_top_i2[t];
    float g1 = g_top_g1[t], g2 = g_top_g2[t];
    int   s1 = g_slot[2 * t], s2 = g_slot[2 * t + 1];
    bool  k1 = (s1 >= 0), k2 = (s2 >= 0);

    float denom = (k1 ? g1 : 0.f) + (k2 ? g2 : 0.f);
    if (denom <= 0.f) return;
    int c = (k1 ? s1 : 0) + (k2 ? s2 : 0);   // locations_s = SUM of slots
    if (c >= CAP) return;                     // one_hot out of range

    if (k1) {
        long long idx = base + ((long long)t * E + i1) * CAP + c;
        if (idx >= lo && idx < hi) out[idx] = weighted ? (g1 / denom) : 1.0f;
    }
    if (k2) {
        long long idx = base + ((long long)t * E + i2) * CAP + c;
        if (idx >= lo && idx < hi) out[idx] = weighted ? (g2 / denom) : 1.0f;
    }
}

__global__ __launch_bounds__(256)
void k4_fill_scatter(float* __restrict__ out, long long osz,
                     long long o_laux, long long o_cw,
                     long long o_dm,   long long o_ec)
{
    const long long lo = (long long)blockIdx.x * CHUNK;
    const long long hi = min(lo + CHUNK, osz);

    // ---- streaming zero-fill of [lo, hi) ----
    {
        long long lo4 = lo >> 2;
        long long hi4 = hi >> 2;
        float4 z = make_float4(0.f, 0.f, 0.f, 0.f);
        float4* o4 = (float4*)out;
        for (long long i = lo4 + threadIdx.x; i < hi4; i += 256)
            __stcs(o4 + i, z);
        if (hi == osz) {
            for (long long i = (hi4 << 2) + threadIdx.x; i < osz; i += 256)
                out[i] = 0.f;
        }
    }
    __syncthreads();

    // ---- patch nonzeros that land inside [lo, hi) ----
    const int tid = threadIdx.x;

    if (o_cw >= 0 && tid < 16) {
        long long sec_lo = o_cw, sec_hi = o_cw + (long long)CW_ELEMS;
        if (hi > sec_lo && lo < sec_hi) {
            long long a = lo > sec_lo ? lo : sec_lo;
            long long b = hi < sec_hi ? hi : sec_hi;
            long long tmin = (a - sec_lo) / ROW;
            long long tmax = (b - 1 - sec_lo) / ROW;
            long long t = tmin + tid;
            if (t <= tmax) patch_token((int)t, out, lo, hi, sec_lo, true);
        }
    }
    if (o_dm >= 0 && tid >= 16 && tid < 32) {
        long long sec_lo = o_dm, sec_hi = o_dm + (long long)CW_ELEMS;
        if (hi > sec_lo && lo < sec_hi) {
            long long a = lo > sec_lo ? lo : sec_lo;
            long long b = hi < sec_hi ? hi : sec_hi;
            long long tmin = (a - sec_lo) / ROW;
            long long tmax = (b - 1 - sec_lo) / ROW;
            long long t = tmin + (tid - 16);
            if (t <= tmax) patch_token((int)t, out, lo, hi, sec_lo, false);
        }
    }
    if (tid == 32 && o_laux >= lo && o_laux < hi) out[o_laux] = g_laux;
    if (o_ec >= 0 && tid >= 64 && tid < 96) {
        int e = tid - 64;
        long long idx = o_ec + e;
        if (idx >= lo && idx < hi) out[idx] = g_ec[e];
    }
}

// ---------------- launch ---------------------------------------------------
extern "C" void kernel_launch(void* const* d_in, const int* in_sizes, int n_in,
                              void* d_out, int out_size)
{
    const float* x  = (const float*)d_in[0];
    const float* wg = (const float*)d_in[1];
    float* out = (float*)d_out;

    const long long CW = (long long)CW_ELEMS;
    long long o_laux = -1, o_cw = -1, o_dm = -1, o_ec = -1;

    long long osz = (long long)out_size;
    if (osz == 1 + 2 * CW + 32) {
        o_laux = 0;
        o_cw   = 1;
        o_dm   = 1 + CW;
        o_ec   = 1 + 2 * CW;
    } else if (osz == 2 * CW) {
        o_cw = 0; o_dm = CW;
    } else if (osz == CW) {
        o_cw = 0;
    } else {
        o_laux = 0;
        o_cw   = 1;
        if (osz > 1 + CW)     o_dm = 1 + CW;
        if (osz > 1 + 2 * CW) o_ec = 1 + 2 * CW;
    }

    k1a_gemm<<<128 * SPLITS, K1_THREADS>>>(x, wg);
    k1b_topk<<<NB2, 1024>>>();
    k3_capacity<<<E + 1, K3_T>>>();

    int fill_blocks = (int)((osz + CHUNK - 1) / CHUNK);
    k4_fill_scatter<<<fill_blocks, 256>>>(out, osz, o_laux, o_cw, o_dm, o_ec);
}

// round 15
// speedup vs baseline: 1.8959x; 1.0267x over previous
#include <cuda_runtime.h>
#include <math.h>
#include <float.h>
#include <stdint.h>

#define S   4096
#define MD  2048
#define E   32
#define CAP 256
#define ROW (E * CAP)                    // 8192 floats per token row-group
#define CW_ELEMS ((size_t)S * E * CAP)   // 33554432

// ---------------- device scratch (no allocations allowed) ----------------
#define SPLITS 8
__device__ float g_part[SPLITS][S * E];   // split-K partial logits (4MB)

__device__ int   g_top_i1[S];
__device__ int   g_top_i2[S];
__device__ float g_top_v1[S];
__device__ float g_top_v2[S];
__device__ float g_top_g1[S];
__device__ float g_top_g2[S];
__device__ int   g_slot[S * 2];

#define NB2 128
__device__ float g_pgsum[NB2 * E];
__device__ int   g_pcnt[NB2 * E];
__device__ float g_laux;
__device__ float g_ec[E];

// ---------------- KA: interleaved GEMM blocks + fill blocks ---------------
#define KA_THREADS 128
#define N_GEMM 1024           // 128 token-groups x 8 splits
#define KC 64
#define KSPAN (MD / SPLITS)   // 256
#define LD4 17                // float4 row stride (16 + 1 pad)
#define CHUNK 65536LL         // floats per fill block (256KB)

__global__ __launch_bounds__(KA_THREADS)
void ka_gemm_fill(const float* __restrict__ x, const float* __restrict__ wg,
                  float* __restrict__ out, long long osz)
{
    __shared__ float4 xs[32 * LD4];
    __shared__ float4 ws[32 * LD4];

    const int bid = blockIdx.x;
    bool is_gemm;
    int  id;
    if (bid < 2 * N_GEMM) {           // interleave gemm/fill across SMs
        is_gemm = !(bid & 1);
        id = bid >> 1;
    } else {                          // extra fill chunks
        is_gemm = false;
        id = bid - N_GEMM;
    }

    if (!is_gemm) {
        // ---- streaming zero-fill of chunk `id` ----
        const long long lo = (long long)id * CHUNK;
        const long long hi = min(lo + CHUNK, osz);
        if (lo >= osz) return;
        long long lo4 = lo >> 2;
        long long hi4 = hi >> 2;
        float4 z = make_float4(0.f, 0.f, 0.f, 0.f);
        float4* o4 = (float4*)out;
        for (long long i = lo4 + threadIdx.x; i < hi4; i += KA_THREADS)
            __stcs(o4 + i, z);
        if (hi == osz) {
            for (long long i = (hi4 << 2) + threadIdx.x; i < osz; i += KA_THREADS)
                out[i] = 0.f;
        }
        return;
    }

    // ---- GEMM: 32 tokens x 32 experts, K-span of 256 ----
    const int split = id & (SPLITS - 1);
    const int tgrp  = id >> 3;
    const int tid = threadIdx.x;
    const int tx  = tid & 7;    // expert lane: experts tx, tx+8, tx+16, tx+24
    const int ty  = tid >> 3;   // token group (2 tokens), 0..15
    const int t0  = tgrp * 32;

    float acc[2][4];
#pragma unroll
    for (int i = 0; i < 2; i++)
#pragma unroll
        for (int j = 0; j < 4; j++) acc[i][j] = 0.f;

    const float4* x4 = (const float4*)x;
    const float4* w4 = (const float4*)wg;

    const int kbeg = split * KSPAN;
    for (int kc = kbeg; kc < kbeg + KSPAN; kc += KC) {
        const int kc4 = kc >> 2;
        for (int i = tid; i < 32 * 16; i += KA_THREADS) {
            int r = i >> 4, c = i & 15;
            xs[r * LD4 + c] = x4[(size_t)(t0 + r) * (MD / 4) + kc4 + c];
            ws[r * LD4 + c] = w4[(size_t)r       * (MD / 4) + kc4 + c];
        }
        __syncthreads();

#pragma unroll
        for (int k4 = 0; k4 < 16; k4++) {
            float4 a0 = xs[(2 * ty)     * LD4 + k4];
            float4 a1 = xs[(2 * ty + 1) * LD4 + k4];
#pragma unroll
            for (int j = 0; j < 4; j++) {
                float4 b = ws[(tx + 8 * j) * LD4 + k4];   // conflict-free
                acc[0][j] = fmaf(a0.x, b.x, fmaf(a0.y, b.y, fmaf(a0.z, b.z, fmaf(a0.w, b.w, acc[0][j]))));
                acc[1][j] = fmaf(a1.x, b.x, fmaf(a1.y, b.y, fmaf(a1.z, b.z, fmaf(a1.w, b.w, acc[1][j]))));
            }
        }
        __syncthreads();
    }

#pragma unroll
    for (int i = 0; i < 2; i++)
#pragma unroll
        for (int j = 0; j < 4; j++)
            g_part[split][(size_t)(t0 + 2 * ty + i) * E + (tx + 8 * j)] = acc[i][j];
}

// ---------------- K1b: reduce splits + top2/softmax + partial sums --------
__global__ __launch_bounds__(1024)
void k1b_topk()
{
    const int warp = threadIdx.x >> 5;
    const int lane = threadIdx.x & 31;
    const int t = blockIdx.x * 32 + warp;
    const size_t o = (size_t)t * E + lane;

    float l = 0.f;
#pragma unroll
    for (int sp = 0; sp < SPLITS; sp++) l += g_part[sp][o];

    // top-1 (tie -> lower index, matching jax.lax.top_k)
    float v1 = l; int i1 = lane;
#pragma unroll
    for (int off = 16; off; off >>= 1) {
        float ov = __shfl_xor_sync(0xffffffffu, v1, off);
        int   oi = __shfl_xor_sync(0xffffffffu, i1, off);
        if (ov > v1 || (ov == v1 && oi < i1)) { v1 = ov; i1 = oi; }
    }
    // top-2
    float l2 = (lane == i1) ? -FLT_MAX : l;
    float v2 = l2; int i2 = lane;
#pragma unroll
    for (int off = 16; off; off >>= 1) {
        float ov = __shfl_xor_sync(0xffffffffu, v2, off);
        int   oi = __shfl_xor_sync(0xffffffffu, i2, off);
        if (ov > v2 || (ov == v2 && oi < i2)) { v2 = ov; i2 = oi; }
    }

    // softmax over the 32 logits
    float p = expf(l - v1);
    float sum = p;
#pragma unroll
    for (int off = 16; off; off >>= 1) sum += __shfl_xor_sync(0xffffffffu, sum, off);
    float gate = p / sum;

    float g1v = __shfl_sync(0xffffffffu, gate, i1);
    float g2v = __shfl_sync(0xffffffffu, gate, i2);

    if (lane == 0) {
        g_top_i1[t] = i1;  g_top_i2[t] = i2;
        g_top_v1[t] = v1;  g_top_v2[t] = v2;
        g_top_g1[t] = g1v; g_top_g2[t] = g2v;
        g_slot[2 * t]     = -1;
        g_slot[2 * t + 1] = -1;
    }

    // deterministic per-block reduction of gate sums / counts
    __shared__ float gm[32][33];
    __shared__ int   im[32];
    gm[warp][lane] = gate;
    if (lane == 0) im[warp] = i1 | (i2 << 8);
    __syncthreads();

    if (warp == 0) {
        float s = 0.f; int c = 0;
#pragma unroll 8
        for (int w = 0; w < 32; w++) {
            s += gm[w][lane];
            int pk = im[w];
            c += ((pk & 255) == lane) + ((pk >> 8) == lane);
        }
        g_pgsum[blockIdx.x * E + lane] = s;
        g_pcnt [blockIdx.x * E + lane] = c;
    }
}

// ---------------- K3: capacity filter + slot assignment (+laux reduce) ----
#define K3_T 1024
#define TPT  (S / K3_T)   // 4 tokens per thread

__global__ __launch_bounds__(K3_T)
void k3_capacity()
{
    const int tid  = threadIdx.x;
    const int lane = tid & 31;
    const int warp = tid >> 5;

    if (blockIdx.x == E) {
        __shared__ float rs[32][33];
        __shared__ int   rc[32][33];
        float s = 0.f; int c = 0;
        for (int b = warp; b < NB2; b += 32) {
            s += g_pgsum[b * E + lane];
            c += g_pcnt [b * E + lane];
        }
        rs[warp][lane] = s; rc[warp][lane] = c;
        __syncthreads();
        if (tid < 32) {
            float st = 0.f; int ct = 0;
#pragma unroll
            for (int k = 0; k < 32; k++) { st += rs[k][tid]; ct += rc[k][tid]; }
            g_ec[tid] = (float)ct;
            float prod = (st / (float)S) * ((float)ct / (float)S);
#pragma unroll
            for (int off = 16; off; off >>= 1) prod += __shfl_xor_sync(0xffffffffu, prod, off);
            if (tid == 0) g_laux = prod * 16.0f;   // *E*E/K/E = *16
        }
        return;
    }

    const int e = blockIdx.x;
    __shared__ float vals[S];
    __shared__ int   s_cnt;
    __shared__ float s_thr;
    __shared__ int   wtot[32];
    __shared__ int   wbase[32];

    if (tid == 0) s_cnt = 0;
    __syncthreads();

    float myv[TPT];
    int   myj[TPT];
#pragma unroll
    for (int k = 0; k < TPT; k++) {
        int t = tid * TPT + k;
        int i1 = g_top_i1[t], i2 = g_top_i2[t];
        int j = (i1 == e) ? 0 : ((i2 == e) ? 1 : -1);
        float v = (j == 0) ? g_top_v1[t] : ((j == 1) ? g_top_v2[t] : 0.f);
        bool cand = (j >= 0 && v > 0.f);
        myj[k] = cand ? j : -1;
        myv[k] = v;
        if (cand) {
            int p = atomicAdd(&s_cnt, 1);
            vals[p] = v;
        }
    }
    __syncthreads();

    const int n = s_cnt;
    if (n > CAP) {
        int n2 = 1; while (n2 < n) n2 <<= 1;
        for (int i = n + tid; i < n2; i += K3_T) vals[i] = -FLT_MAX;
        __syncthreads();
        for (int k = 2; k <= n2; k <<= 1) {
            for (int j = k >> 1; j > 0; j >>= 1) {
                for (int i = tid; i < n2; i += K3_T) {
                    int ixj = i ^ j;
                    if (ixj > i) {
                        float a = vals[i], b = vals[ixj];
                        bool desc = ((i & k) == 0);
                        if (desc ? (a < b) : (a > b)) { vals[i] = b; vals[ixj] = a; }
                    }
                }
                __syncthreads();
            }
        }
    }
    if (tid == 0) s_thr = (n > CAP) ? vals[CAP - 1] : -FLT_MAX;
    __syncthreads();
    const float thr = s_thr;

    int kept = 0;
    bool kf[TPT];
#pragma unroll
    for (int k = 0; k < TPT; k++) {
        kf[k] = (myj[k] >= 0) && (myv[k] >= thr);
        kept += kf[k];
    }

    int inc = kept;
#pragma unroll
    for (int off = 1; off < 32; off <<= 1) {
        int nb = __shfl_up_sync(0xffffffffu, inc, off);
        if (lane >= off) inc += nb;
    }
    int exc = inc - kept;
    if (lane == 31) wtot[warp] = inc;
    __syncthreads();

    if (warp == 0) {
        int v = wtot[lane];
        int iv = v;
#pragma unroll
        for (int off = 1; off < 32; off <<= 1) {
            int nb = __shfl_up_sync(0xffffffffu, iv, off);
            if (lane >= off) iv += nb;
        }
        wbase[lane] = iv - v;
    }
    __syncthreads();

    int slot = wbase[warp] + exc;
#pragma unroll
    for (int k = 0; k < TPT; k++) {
        if (kf[k]) {
            int t = tid * TPT + k;
            g_slot[2 * t + myj[k]] = slot++;
        }
    }
}

// ---------------- KD: scatter-only patch ----------------------------------
__global__ __launch_bounds__(128)
void kd_scatter(float* __restrict__ out,
                long long o_laux, long long o_cw,
                long long o_dm,   long long o_ec)
{
    const int tid = threadIdx.x;
    if (blockIdx.x == 0) {
        if (tid == 32 && o_laux >= 0) out[o_laux] = g_laux;
        if (tid < 32 && o_ec >= 0)    out[o_ec + tid] = g_ec[tid];
    }

    int t = blockIdx.x * 128 + tid;
    if (t >= S) return;

    int   i1 = g_top_i1[t], i2 = g_top_i2[t];
    float g1 = g_top_g1[t], g2 = g_top_g2[t];
    int   s1 = g_slot[2 * t], s2 = g_slot[2 * t + 1];
    bool  k1 = (s1 >= 0), k2 = (s2 >= 0);

    float denom = (k1 ? g1 : 0.f) + (k2 ? g2 : 0.f);
    if (denom <= 0.f) return;
    int c = (k1 ? s1 : 0) + (k2 ? s2 : 0);   // locations_s = SUM of slots
    if (c >= CAP) return;                     // one_hot out of range

    if (k1) {
        long long idx = ((long long)t * E + i1) * CAP + c;
        if (o_cw >= 0) out[o_cw + idx] = g1 / denom;
        if (o_dm >= 0) out[o_dm + idx] = 1.0f;
    }
    if (k2) {
        long long idx = ((long long)t * E + i2) * CAP + c;
        if (o_cw >= 0) out[o_cw + idx] = g2 / denom;
        if (o_dm >= 0) out[o_dm + idx] = 1.0f;
    }
}

// ---------------- launch ---------------------------------------------------
extern "C" void kernel_launch(void* const* d_in, const int* in_sizes, int n_in,
                              void* d_out, int out_size)
{
    const float* x  = (const float*)d_in[0];
    const float* wg = (const float*)d_in[1];
    float* out = (float*)d_out;

    const long long CW = (long long)CW_ELEMS;
    long long o_laux = -1, o_cw = -1, o_dm = -1, o_ec = -1;

    long long osz = (long long)out_size;
    if (osz == 1 + 2 * CW + 32) {
        o_laux = 0;
        o_cw   = 1;
        o_dm   = 1 + CW;
        o_ec   = 1 + 2 * CW;
    } else if (osz == 2 * CW) {
        o_cw = 0; o_dm = CW;
    } else if (osz == CW) {
        o_cw = 0;
    } else {
        o_laux = 0;
        o_cw   = 1;
        if (osz > 1 + CW)     o_dm = 1 + CW;
        if (osz > 1 + 2 * CW) o_ec = 1 + 2 * CW;
    }

    int n_fill = (int)((osz + CHUNK - 1) / CHUNK);   // >= N_GEMM for this shape
    int grid_a = N_GEMM + n_fill;

    ka_gemm_fill<<<grid_a, KA_THREADS>>>(x, wg, out, osz);
    k1b_topk<<<NB2, 1024>>>();
    k3_capacity<<<E + 1, K3_T>>>();
    kd_scatter<<<(S + 127) / 128, 128>>>(out, o_laux, o_cw, o_dm, o_ec);
}